// round 3
// baseline (speedup 1.0000x reference)
#include <cuda_runtime.h>
#include <math.h>

#define T_STEPS 4096
#define NC 4880
#define VD 512
#define HD 512
#define G3 1536
#define NB 64     // blocks in scan kernel (must divide 512)

// ---------------- scratch (device globals; no allocation) ----------------
__device__ float d_visit[T_STEPS * VD];      // 8 MB
__device__ float d_gi[T_STEPS * G3];         // 24 MB
__device__ float d_hs[T_STEPS * HD];         // 8 MB
__device__ float d_hbuf[2][HD];
__device__ float d_logits[T_STEPS];
__device__ float d_alpha[T_STEPS];
__device__ float d_part[NB * HD];
__device__ unsigned d_barcnt;
__device__ unsigned d_bargen;

// ---------------- helpers ----------------
__device__ __forceinline__ unsigned ld_acq(const unsigned* p) {
    unsigned v;
    asm volatile("ld.acquire.gpu.u32 %0, [%1];" : "=r"(v) : "l"(p) : "memory");
    return v;
}
__device__ __forceinline__ void st_rel(unsigned* p, unsigned v) {
    asm volatile("st.release.gpu.u32 [%0], %1;" :: "l"(p), "r"(v) : "memory");
}

// ============================================================
// GEMM1: d_visit[t][d] = sum_c H[c][t] * X[c][d]
// H: (NC, T) row-major, X: (NC, VD) row-major. Both K(=c)-major -> no transpose.
// 128x128 tile, BK=8, 256 threads, 8x8 per thread.
// ============================================================
__global__ __launch_bounds__(256) void gemm1_kernel(const float* __restrict__ Hm,
                                                    const float* __restrict__ Xe) {
    __shared__ __align__(16) float As[8][128];
    __shared__ __align__(16) float Bs[8][128];
    const int t0 = blockIdx.x * 128;
    const int d0 = blockIdx.y * 128;
    const int tid = threadIdx.x;
    const int kk = tid >> 5;           // 0..7
    const int c4 = (tid & 31) << 2;    // 0..124
    const int ty = (tid >> 4) << 3;    // 0..120
    const int tx = (tid & 15) << 3;    // 0..120

    float acc[8][8];
#pragma unroll
    for (int i = 0; i < 8; i++)
#pragma unroll
        for (int j = 0; j < 8; j++) acc[i][j] = 0.f;

    for (int c0 = 0; c0 < NC; c0 += 8) {
        *(float4*)&As[kk][c4] = *(const float4*)&Hm[(size_t)(c0 + kk) * T_STEPS + t0 + c4];
        *(float4*)&Bs[kk][c4] = *(const float4*)&Xe[(size_t)(c0 + kk) * VD + d0 + c4];
        __syncthreads();
#pragma unroll
        for (int k = 0; k < 8; k++) {
            float a[8], b[8];
            *(float4*)&a[0] = *(float4*)&As[k][ty];
            *(float4*)&a[4] = *(float4*)&As[k][ty + 4];
            *(float4*)&b[0] = *(float4*)&Bs[k][tx];
            *(float4*)&b[4] = *(float4*)&Bs[k][tx + 4];
#pragma unroll
            for (int i = 0; i < 8; i++)
#pragma unroll
                for (int j = 0; j < 8; j++) acc[i][j] = fmaf(a[i], b[j], acc[i][j]);
        }
        __syncthreads();
    }
#pragma unroll
    for (int i = 0; i < 8; i++)
#pragma unroll
        for (int j = 0; j < 8; j += 4) {
            float4 v = make_float4(acc[i][j], acc[i][j + 1], acc[i][j + 2], acc[i][j + 3]);
            *(float4*)&d_visit[(size_t)(t0 + ty + i) * VD + d0 + tx + j] = v;
        }
}

// ============================================================
// GEMM2: d_gi[t][g] = sum_k d_visit[t][k] * W_ih[g][k] + b_ih[g]
// NT gemm: transpose-on-load into smem. 128x128 tile, BK=8.
// ============================================================
__global__ __launch_bounds__(256) void gemm2_kernel(const float* __restrict__ Wih,
                                                    const float* __restrict__ bih) {
    __shared__ __align__(16) float As[8][132];
    __shared__ __align__(16) float Bs[8][132];
    const int t0 = blockIdx.x * 128;
    const int g0 = blockIdx.y * 128;
    const int tid = threadIdx.x;
    const int row = tid >> 1;         // 0..127
    const int kc = (tid & 1) << 2;    // 0 or 4
    const int ty = (tid >> 4) << 3;
    const int tx = (tid & 15) << 3;

    float acc[8][8];
#pragma unroll
    for (int i = 0; i < 8; i++)
#pragma unroll
        for (int j = 0; j < 8; j++) acc[i][j] = 0.f;

    for (int k0 = 0; k0 < VD; k0 += 8) {
        float4 av = *(const float4*)&d_visit[(size_t)(t0 + row) * VD + k0 + kc];
        float4 bv = *(const float4*)&Wih[(size_t)(g0 + row) * VD + k0 + kc];
        As[kc + 0][row] = av.x; As[kc + 1][row] = av.y;
        As[kc + 2][row] = av.z; As[kc + 3][row] = av.w;
        Bs[kc + 0][row] = bv.x; Bs[kc + 1][row] = bv.y;
        Bs[kc + 2][row] = bv.z; Bs[kc + 3][row] = bv.w;
        __syncthreads();
#pragma unroll
        for (int k = 0; k < 8; k++) {
            float a[8], b[8];
            *(float4*)&a[0] = *(float4*)&As[k][ty];
            *(float4*)&a[4] = *(float4*)&As[k][ty + 4];
            *(float4*)&b[0] = *(float4*)&Bs[k][tx];
            *(float4*)&b[4] = *(float4*)&Bs[k][tx + 4];
#pragma unroll
            for (int i = 0; i < 8; i++)
#pragma unroll
                for (int j = 0; j < 8; j++) acc[i][j] = fmaf(a[i], b[j], acc[i][j]);
        }
        __syncthreads();
    }
#pragma unroll
    for (int i = 0; i < 8; i++)
#pragma unroll
        for (int j = 0; j < 8; j++) {
            d_gi[(size_t)(t0 + ty + i) * G3 + g0 + tx + j] = acc[i][j] + bih[g0 + tx + j];
        }
}

// ============================================================
// init: zero h0 buffer + reset grid barrier state (graph-replay safe)
// ============================================================
__global__ void init_kernel() {
    if (threadIdx.x == 0) { d_barcnt = 0; d_bargen = 0; }
    d_hbuf[0][threadIdx.x] = 0.f;
}

// ============================================================
// GRU scan: NB=64 blocks (all co-resident), 256 threads.
// Each block owns 8 outputs j = blk*8+w (one per warp), rows {j, j+512, j+1024}
// of W_hh staged in SMEM (24 rows x 512 = 48 KB).
// h exchanged through L2 (__ldcg to avoid stale L1); sense-reversing grid barrier.
// ============================================================
__global__ __launch_bounds__(256) void gru_scan_kernel(const float* __restrict__ Whh,
                                                       const float* __restrict__ bhh) {
    __shared__ __align__(16) float Ws[24][512];
    const int tid = threadIdx.x;
    const int blk = blockIdx.x;
    const int w = tid >> 5;
    const int l = tid & 31;
    const int j = blk * 8 + w;   // this warp's output index, < 512

    // stage W_hh slice: smem row rr = o*3+g  <->  global row blk*8+o + g*512
    for (int i = tid; i < 24 * 128; i += 256) {
        int rr = i >> 7;
        int c4 = (i & 127) << 2;
        int o = rr / 3;
        int g = rr - o * 3;
        int G = blk * 8 + o + g * 512;
        *(float4*)&Ws[rr][c4] = *(const float4*)&Whh[(size_t)G * HD + c4];
    }
    const float br = bhh[j];
    const float bz = bhh[j + 512];
    const float bn = bhh[j + 1024];
    // gi for t=0 (prefetched)
    float gr = d_gi[j], gz = d_gi[j + 512], gn = d_gi[j + 1024];
    __syncthreads();

    unsigned gen = 0;
    for (int t = 0; t < T_STEPS; t++) {
        const int p = t & 1;
        const float* hb = d_hbuf[p];

        // load h (L2-fresh) : 16 floats/lane
        float4 hv[4];
#pragma unroll
        for (int q = 0; q < 4; q++) hv[q] = __ldcg((const float4*)(hb + 4 * (l + 32 * q)));
        float hprev = __ldcg(hb + j);

        // prefetch gi for t+1 (broadcast loads)
        float gr2 = 0.f, gz2 = 0.f, gn2 = 0.f;
        if (t + 1 < T_STEPS) {
            const float* gp = d_gi + (size_t)(t + 1) * G3 + j;
            gr2 = __ldg(gp); gz2 = __ldg(gp + 512); gn2 = __ldg(gp + 1024);
        }

        // three dot products over HD=512
        float ar = 0.f, az = 0.f, an = 0.f;
#pragma unroll
        for (int q = 0; q < 4; q++) {
            const int c = 4 * (l + 32 * q);
            float4 wr = *(const float4*)&Ws[3 * w + 0][c];
            float4 wzv = *(const float4*)&Ws[3 * w + 1][c];
            float4 wn = *(const float4*)&Ws[3 * w + 2][c];
            float4 h = hv[q];
            ar = fmaf(wr.x, h.x, fmaf(wr.y, h.y, fmaf(wr.z, h.z, fmaf(wr.w, h.w, ar))));
            az = fmaf(wzv.x, h.x, fmaf(wzv.y, h.y, fmaf(wzv.z, h.z, fmaf(wzv.w, h.w, az))));
            an = fmaf(wn.x, h.x, fmaf(wn.y, h.y, fmaf(wn.z, h.z, fmaf(wn.w, h.w, an))));
        }
#pragma unroll
        for (int off = 16; off; off >>= 1) {
            ar += __shfl_xor_sync(0xffffffffu, ar, off);
            az += __shfl_xor_sync(0xffffffffu, az, off);
            an += __shfl_xor_sync(0xffffffffu, an, off);
        }

        float r = 1.f / (1.f + expf(-(gr + ar + br)));
        float z = 1.f / (1.f + expf(-(gz + az + bz)));
        float n = tanhf(gn + r * (an + bn));
        float hnew = (1.f - z) * n + z * hprev;
        if (l == 0) {
            d_hbuf[p ^ 1][j] = hnew;
            d_hs[(size_t)t * HD + j] = hnew;
        }
        gr = gr2; gz = gz2; gn = gn2;

        // ---- grid barrier (sense-reversing, local generation counter) ----
        __syncthreads();
        if (tid == 0) {
            __threadfence();
            unsigned arr = atomicAdd(&d_barcnt, 1u);
            if (arr == NB - 1) {
                atomicExch(&d_barcnt, 0u);
                st_rel(&d_bargen, gen + 1u);
            } else {
                while (ld_acq(&d_bargen) < gen + 1u) {}
            }
        }
        __syncthreads();
        gen++;
    }
}

// ============================================================
// attention: logits, softmax, deterministic 2-stage weighted sum
// ============================================================
__global__ __launch_bounds__(256) void att_logits_kernel(const float* __restrict__ watt) {
    const int t = blockIdx.x * 8 + (threadIdx.x >> 5);
    const int l = threadIdx.x & 31;
    const float* hp = d_hs + (size_t)t * HD;
    float acc = 0.f;
#pragma unroll
    for (int q = 0; q < 4; q++) {
        const int c = 4 * (l + 32 * q);
        float4 h = *(const float4*)(hp + c);
        float4 wv = *(const float4*)(watt + c);
        acc = fmaf(h.x, wv.x, fmaf(h.y, wv.y, fmaf(h.z, wv.z, fmaf(h.w, wv.w, acc))));
    }
#pragma unroll
    for (int off = 16; off; off >>= 1) acc += __shfl_xor_sync(0xffffffffu, acc, off);
    if (l == 0) d_logits[t] = acc;
}

__global__ __launch_bounds__(1024) void att_softmax_kernel() {
    __shared__ float sh[32];
    const int tid = threadIdx.x;
    const int l = tid & 31, w = tid >> 5;

    float m = -1e30f;
    for (int i = tid; i < T_STEPS; i += 1024) m = fmaxf(m, d_logits[i]);
#pragma unroll
    for (int off = 16; off; off >>= 1) m = fmaxf(m, __shfl_xor_sync(0xffffffffu, m, off));
    if (l == 0) sh[w] = m;
    __syncthreads();
    if (tid < 32) {
        float v = sh[tid];
#pragma unroll
        for (int off = 16; off; off >>= 1) v = fmaxf(v, __shfl_xor_sync(0xffffffffu, v, off));
        if (tid == 0) sh[0] = v;
    }
    __syncthreads();
    const float mall = sh[0];
    __syncthreads();

    float s = 0.f;
    for (int i = tid; i < T_STEPS; i += 1024) s += expf(d_logits[i] - mall);
#pragma unroll
    for (int off = 16; off; off >>= 1) s += __shfl_xor_sync(0xffffffffu, s, off);
    if (l == 0) sh[w] = s;
    __syncthreads();
    if (tid < 32) {
        float v = sh[tid];
#pragma unroll
        for (int off = 16; off; off >>= 1) v += __shfl_xor_sync(0xffffffffu, v, off);
        if (tid == 0) sh[0] = v;
    }
    __syncthreads();
    const float inv = 1.f / sh[0];
    for (int i = tid; i < T_STEPS; i += 1024) d_alpha[i] = expf(d_logits[i] - mall) * inv;
}

__global__ __launch_bounds__(512) void att_part_kernel() {
    const int d = threadIdx.x;
    const int b = blockIdx.x;
    float acc = 0.f;
    const int tbeg = b * (T_STEPS / NB);
    for (int t = tbeg; t < tbeg + (T_STEPS / NB); t++)
        acc = fmaf(d_alpha[t], d_hs[(size_t)t * HD + d], acc);
    d_part[b * HD + d] = acc;
}

__global__ __launch_bounds__(512) void att_final_kernel(float* __restrict__ out) {
    const int d = threadIdx.x;
    float acc = 0.f;
#pragma unroll 4
    for (int b = 0; b < NB; b++) acc += d_part[b * HD + d];
    out[d] = acc;
}

// ============================================================
extern "C" void kernel_launch(void* const* d_in, const int* in_sizes, int n_in,
                              void* d_out, int out_size) {
    const float* Hm   = (const float*)d_in[0];
    // d_in[1] = TE (unused by reference)
    const float* Xe   = (const float*)d_in[2];
    const float* Wih  = (const float*)d_in[3];
    const float* Whh  = (const float*)d_in[4];
    const float* bih  = (const float*)d_in[5];
    const float* bhh  = (const float*)d_in[6];
    const float* watt = (const float*)d_in[7];
    float* out = (float*)d_out;

    gemm1_kernel<<<dim3(T_STEPS / 128, VD / 128), 256>>>(Hm, Xe);
    gemm2_kernel<<<dim3(T_STEPS / 128, G3 / 128), 256>>>(Wih, bih);
    init_kernel<<<1, 512>>>();
    gru_scan_kernel<<<NB, 256>>>(Whh, bhh);
    att_logits_kernel<<<T_STEPS / 8, 256>>>(watt);
    att_softmax_kernel<<<1, 1024>>>();
    att_part_kernel<<<NB, 512>>>();
    att_final_kernel<<<1, 512>>>(out);
}